// round 1
// baseline (speedup 1.0000x reference)
#include <cuda_runtime.h>

// Problem constants
#define B_   8
#define S_   4096
#define H_   16
#define Dm   64
#define D2m  128
#define HIDm (H_ * Dm)
#define NROWS (B_ * H_ * S_)
#define TPB  64
#define EPSf 1e-5f

// dot(w[0:64], x[0:64]) with 4 independent partial-sum chains (ILP).
__device__ __forceinline__ float dot64(const float* __restrict__ w, const float (&x)[64]) {
    float a0 = 0.f, a1 = 0.f, a2 = 0.f, a3 = 0.f;
    const float4* w4 = reinterpret_cast<const float4*>(w);
#pragma unroll
    for (int i = 0; i < 16; i++) {
        float4 ww = w4[i];
        a0 = fmaf(ww.x, x[4 * i + 0], a0);
        a1 = fmaf(ww.y, x[4 * i + 1], a1);
        a2 = fmaf(ww.z, x[4 * i + 2], a2);
        a3 = fmaf(ww.w, x[4 * i + 3], a3);
    }
    return (a0 + a1) + (a2 + a3);
}

__device__ __forceinline__ void load64(float (&x)[64], const float* __restrict__ p) {
    const float4* s4 = reinterpret_cast<const float4*>(p);
#pragma unroll
    for (int i = 0; i < 16; i++) {
        float4 t = s4[i];
        x[4 * i + 0] = t.x; x[4 * i + 1] = t.y;
        x[4 * i + 2] = t.z; x[4 * i + 3] = t.w;
    }
}

__global__ void __launch_bounds__(TPB) mhba_fused_kernel(
    const float* __restrict__ Qin, const float* __restrict__ Kin,
    const float* __restrict__ Vin, const float* __restrict__ MEM,
    const float* __restrict__ Wq,  const float* __restrict__ Wk,
    const float* __restrict__ Wv,  const float* __restrict__ FG,
    const float* __restrict__ LN1W, const float* __restrict__ LN1B,
    const float* __restrict__ W1,
    const float* __restrict__ LN2W, const float* __restrict__ LN2B,
    const float* __restrict__ W2,  const float* __restrict__ B2,
    float* __restrict__ OUT, float* __restrict__ CM)
{
    // Per-thread 128-float scratch, layout buf[e*TPB + tid]: lanes in a warp hit
    // consecutive 4B addresses -> conflict-free. Strictly thread-private, no syncs.
    __shared__ float buf[D2m * TPB];
    const int tid = threadIdx.x;
    const int r   = blockIdx.x * TPB + tid;   // row id in memorys order: ((b*H+h)*S+s)
    const int s   = r & (S_ - 1);
    const int h   = (r >> 12) & (H_ - 1);
    const int b   = r >> 16;
    const int qoff = ((b * S_ + s) * H_ + h) * Dm;  // q/k/v/out row offset
    const int moff = r * Dm;                        // memorys/cur_mem row offset

    float x[64];

    // ---------------- kp = x_k @ Wk^T  -> buf ----------------
    load64(x, Kin + qoff);
#pragma unroll 1
    for (int e = 0; e < Dm; e += 2) {
        buf[e * TPB + tid]       = dot64(Wk + e * Dm, x);
        buf[(e + 1) * TPB + tid] = dot64(Wk + (e + 1) * Dm, x);
    }

    // ------- vp = x_v @ Wv^T; gate with kp & mem -> cur_mem (output) -------
    load64(x, Vin + qoff);
#pragma unroll 1
    for (int e = 0; e < Dm; e += 2) {
        float vp0 = dot64(Wv + e * Dm, x);
        float vp1 = dot64(Wv + (e + 1) * Dm, x);
        float2 m  = *reinterpret_cast<const float2*>(MEM + moff + e);
        float2 fg = *reinterpret_cast<const float2*>(FG + e);
        float kp0 = buf[e * TPB + tid];
        float kp1 = buf[(e + 1) * TPB + tid];
        float fm0 = fg.x * m.x;
        float fm1 = fg.y * m.y;
        float cell0 = fmaf(kp0, vp0, fm0);
        float cell1 = fmaf(kp1, vp1, fm1);
        float cm0 = fmaf(1.f - fg.x, cell0, fm0);
        float cm1 = fmaf(1.f - fg.y, cell1, fm1);
        *reinterpret_cast<float2*>(CM + moff + e) = make_float2(cm0, cm1);
        buf[e * TPB + tid]       = cm0;
        buf[(e + 1) * TPB + tid] = cm1;
    }

    // ------- qp = x_q @ Wq^T; cv = qp * cur_mem; LN1 stats -------
    load64(x, Qin + qoff);
    float sum = 0.f, sq = 0.f;
#pragma unroll 1
    for (int e = 0; e < Dm; e += 2) {
        float qp0 = dot64(Wq + e * Dm, x);
        float qp1 = dot64(Wq + (e + 1) * Dm, x);
        float cv0 = qp0 * buf[e * TPB + tid];
        float cv1 = qp1 * buf[(e + 1) * TPB + tid];
        buf[e * TPB + tid]       = cv0;
        buf[(e + 1) * TPB + tid] = cv1;
        sum += cv0 + cv1;
        sq  = fmaf(cv0, cv0, sq);
        sq  = fmaf(cv1, cv1, sq);
    }
    float mu  = sum * (1.f / 64.f);
    float var = sq * (1.f / 64.f) - mu * mu;
    float rs  = rsqrtf(var + EPSf);

    // Normalized cv back into registers (constant-indexed -> full unroll).
#pragma unroll
    for (int d = 0; d < Dm; d++)
        x[d] = fmaf((buf[d * TPB + tid] - mu) * rs, LN1W[d], LN1B[d]);

    // ---------------- h1 = ln1(cv) @ W1^T  (128 outs) + LN2 stats ----------------
    float sum2 = 0.f, sq2 = 0.f;
#pragma unroll 1
    for (int e = 0; e < D2m; e += 2) {
        float t0 = dot64(W1 + e * Dm, x);
        float t1 = dot64(W1 + (e + 1) * Dm, x);
        buf[e * TPB + tid]       = t0;
        buf[(e + 1) * TPB + tid] = t1;
        sum2 += t0 + t1;
        sq2 = fmaf(t0, t0, sq2);
        sq2 = fmaf(t1, t1, sq2);
    }
    float mu2 = sum2 * (1.f / 128.f);
    float rs2 = rsqrtf(sq2 * (1.f / 128.f) - mu2 * mu2 + EPSf);

    // Normalize h1 in place.
#pragma unroll 1
    for (int e = 0; e < D2m; e++) {
        float t = buf[e * TPB + tid];
        buf[e * TPB + tid] = fmaf((t - mu2) * rs2, LN2W[e], LN2B[e]);
    }

    // ---------------- mixed[d] = sum_e ln2(h1)[e] * W2[d,e] + b2[d] ----------------
#pragma unroll 1
    for (int dg = 0; dg < Dm; dg += 8) {
        float acc[8];
#pragma unroll
        for (int i = 0; i < 8; i++) acc[i] = B2[dg + i];
#pragma unroll 1
        for (int e = 0; e < D2m; e += 4) {
            float t0 = buf[(e + 0) * TPB + tid];
            float t1 = buf[(e + 1) * TPB + tid];
            float t2 = buf[(e + 2) * TPB + tid];
            float t3 = buf[(e + 3) * TPB + tid];
#pragma unroll
            for (int i = 0; i < 8; i++) {
                float4 w = *reinterpret_cast<const float4*>(W2 + (dg + i) * D2m + e);
                acc[i] = fmaf(w.x, t0, acc[i]);
                acc[i] = fmaf(w.y, t1, acc[i]);
                acc[i] = fmaf(w.z, t2, acc[i]);
                acc[i] = fmaf(w.w, t3, acc[i]);
            }
        }
        *reinterpret_cast<float4*>(OUT + qoff + dg)     = make_float4(acc[0], acc[1], acc[2], acc[3]);
        *reinterpret_cast<float4*>(OUT + qoff + dg + 4) = make_float4(acc[4], acc[5], acc[6], acc[7]);
    }
}

extern "C" void kernel_launch(void* const* d_in, const int* in_sizes, int n_in,
                              void* d_out, int out_size) {
    // metadata order: queries, keys, values, memorys, Wq, Wk, Wv, forget_gate,
    //                 ln1_w, ln1_b, W1, ln2_w, ln2_b, W2, b2
    const float* Qin  = (const float*)d_in[0];
    const float* Kin  = (const float*)d_in[1];
    const float* Vin  = (const float*)d_in[2];
    const float* MEM  = (const float*)d_in[3];
    const float* Wq   = (const float*)d_in[4];
    const float* Wk   = (const float*)d_in[5];
    const float* Wv   = (const float*)d_in[6];
    const float* FG   = (const float*)d_in[7];
    const float* LN1W = (const float*)d_in[8];
    const float* LN1B = (const float*)d_in[9];
    const float* W1   = (const float*)d_in[10];
    const float* LN2W = (const float*)d_in[11];
    const float* LN2B = (const float*)d_in[12];
    const float* W2   = (const float*)d_in[13];
    const float* B2   = (const float*)d_in[14];

    float* OUT = (float*)d_out;                            // [B,S,HID]
    float* CM  = OUT + (size_t)B_ * S_ * H_ * Dm;          // [B,H,S,D]

    mhba_fused_kernel<<<NROWS / TPB, TPB>>>(
        Qin, Kin, Vin, MEM, Wq, Wk, Wv, FG,
        LN1W, LN1B, W1, LN2W, LN2B, W2, B2, OUT, CM);
}

// round 2
// speedup vs baseline: 1.8119x; 1.8119x over previous
#include <cuda_runtime.h>

// Problem constants
#define B_   8
#define S_   4096
#define H_   16
#define Dm   64
#define D2m  128
#define NROWS (B_ * S_ * H_)
#define TPB  128
#define EPSf 1e-5f
#define BUFSTRIDE 66   // u64 per-thread scratch row: 64 pairs + 2 pad (528B, conflict-free LDS.128)

typedef unsigned long long u64;

// ---------- packed f32x2 helpers ----------
__device__ __forceinline__ u64 ffma2(u64 a, u64 b, u64 c) {
    u64 d; asm("fma.rn.f32x2 %0, %1, %2, %3;" : "=l"(d) : "l"(a), "l"(b), "l"(c)); return d;
}
__device__ __forceinline__ u64 fmul2(u64 a, u64 b) {
    u64 d; asm("mul.rn.f32x2 %0, %1, %2;" : "=l"(d) : "l"(a), "l"(b)); return d;
}
__device__ __forceinline__ u64 fadd2(u64 a, u64 b) {
    u64 d; asm("add.rn.f32x2 %0, %1, %2;" : "=l"(d) : "l"(a), "l"(b)); return d;
}
__device__ __forceinline__ u64 pack2(float lo, float hi) {
    u64 d; asm("mov.b64 %0, {%1, %2};" : "=l"(d) : "f"(lo), "f"(hi)); return d;
}
__device__ __forceinline__ float2 unpack2(u64 a) {
    float lo, hi; asm("mov.b64 {%0, %1}, %2;" : "=f"(lo), "=f"(hi) : "l"(a));
    return make_float2(lo, hi);
}
__device__ __forceinline__ float hsum2(u64 a) { float2 f = unpack2(a); return f.x + f.y; }

// dot of 64 floats: weights = 32 packed pairs in SMEM (broadcast LDS.128),
// x = 32 packed pairs in registers. 4 independent packed chains.
__device__ __forceinline__ float dot64p(const u64* __restrict__ w, const u64 (&x)[32]) {
    const ulonglong2* w2 = reinterpret_cast<const ulonglong2*>(w);
    u64 a0 = 0, a1 = 0, a2 = 0, a3 = 0;
#pragma unroll
    for (int i = 0; i < 8; i++) {
        ulonglong2 wa = w2[2 * i];
        ulonglong2 wb = w2[2 * i + 1];
        a0 = ffma2(wa.x, x[4 * i + 0], a0);
        a1 = ffma2(wa.y, x[4 * i + 1], a1);
        a2 = ffma2(wb.x, x[4 * i + 2], a2);
        a3 = ffma2(wb.y, x[4 * i + 3], a3);
    }
    return hsum2(fadd2(fadd2(a0, a1), fadd2(a2, a3)));
}

__device__ __forceinline__ void loadx(u64 (&x)[32], const float* __restrict__ p) {
    const ulonglong2* p2 = reinterpret_cast<const ulonglong2*>(p);
#pragma unroll
    for (int i = 0; i < 16; i++) { ulonglong2 t = p2[i]; x[2 * i] = t.x; x[2 * i + 1] = t.y; }
}

// cooperative gmem->smem stage (floats, vectorized)
__device__ __forceinline__ void stageW(u64* dst, const float* __restrict__ src, int nfloats, int tid) {
    const ulonglong2* s2 = reinterpret_cast<const ulonglong2*>(src);
    ulonglong2* d2 = reinterpret_cast<ulonglong2*>(dst);
#pragma unroll 1
    for (int i = tid; i < nfloats / 4; i += TPB) d2[i] = s2[i];
}

__global__ void __launch_bounds__(TPB) mhba_fused_kernel(
    const float* __restrict__ Qin, const float* __restrict__ Kin,
    const float* __restrict__ Vin, const float* __restrict__ MEM,
    const float* __restrict__ Wq,  const float* __restrict__ Wk,
    const float* __restrict__ Wv,  const float* __restrict__ FG,
    const float* __restrict__ LN1W, const float* __restrict__ LN1B,
    const float* __restrict__ W1,
    const float* __restrict__ LN2W, const float* __restrict__ LN2B,
    const float* __restrict__ W2,  const float* __restrict__ B2,
    float* __restrict__ OUT, float* __restrict__ CM)
{
    extern __shared__ u64 sm[];
    u64*   wS  = sm;            // 4096 u64 = 32KB weight staging
    u64*   pS  = sm + 4096;     // params (packed pairs): fg@0, omfg@32, l1w@64, l1b@96, l2w@128, l2b@192, b2@256 (u64 units)
    float* pSf = (float*)pS;
    u64*   buf = sm + 4096 + 320;  // per-thread scratch: TPB * BUFSTRIDE u64

    const int tid = threadIdx.x;
    u64* myb = buf + tid * BUFSTRIDE;

    // ---- stage params (fg, 1-fg, ln1, ln2, b2) + first weights (Wk, Wv) ----
#pragma unroll 1
    for (int i = tid; i < 64; i += TPB) {
        float g = FG[i];
        pSf[i]       = g;
        pSf[64 + i]  = 1.0f - g;
        pSf[128 + i] = LN1W[i];
        pSf[192 + i] = LN1B[i];
        pSf[512 + i] = B2[i];
    }
#pragma unroll 1
    for (int i = tid; i < 128; i += TPB) {
        pSf[256 + i] = LN2W[i];
        pSf[384 + i] = LN2B[i];
    }
    stageW(wS,        Wk, Dm * Dm, tid);
    stageW(wS + 2048, Wv, Dm * Dm, tid);
    __syncthreads();

    // row mapping
    const int r = blockIdx.x * TPB + tid;       // ((b*H+h)*S+s)
    const int s = r & (S_ - 1);
    const int h = (r >> 12) & (H_ - 1);
    const int b = r >> 16;
    const int qoff = ((b * S_ + s) * H_ + h) * Dm;  // q/k/v/out row offset
    const int moff = r * Dm;                        // memorys/cur_mem row offset

    u64 x2[32];

    // ================= Phase A: kp =================
    loadx(x2, Kin + qoff);
#pragma unroll 1
    for (int ep = 0; ep < 32; ep++) {
        float k0 = dot64p(wS + (2 * ep)     * 32, x2);
        float k1 = dot64p(wS + (2 * ep + 1) * 32, x2);
        myb[ep] = pack2(k0, k1);
    }

    // ================= Phase A: vp, gate -> cur_mem =================
    loadx(x2, Vin + qoff);
    {
        const u64* memp = (const u64*)(MEM + moff);
        u64* cmo = (u64*)(CM + moff);
        const u64* fgp   = pS;
        const u64* omfgp = pS + 32;
#pragma unroll 1
        for (int ep = 0; ep < 32; ep += 2) {
            u64 cms[2];
#pragma unroll
            for (int t = 0; t < 2; t++) {
                int j = ep + t;
                float va = dot64p(wS + 2048 + (2 * j)     * 32, x2);
                float vb = dot64p(wS + 2048 + (2 * j + 1) * 32, x2);
                u64 vp   = pack2(va, vb);
                u64 m    = memp[j];
                u64 fgm  = fmul2(fgp[j], m);
                u64 cell = ffma2(myb[j], vp, fgm);
                u64 cm   = ffma2(omfgp[j], cell, fgm);
                myb[j] = cm;
                cms[t] = cm;
            }
            ulonglong2 st; st.x = cms[0]; st.y = cms[1];
            *(ulonglong2*)(cmo + ep) = st;
        }
    }

    __syncthreads();
    stageW(wS, Wq, Dm * Dm, tid);
    __syncthreads();

    // ================= Phase A: qp, cv, LN1 =================
    loadx(x2, Qin + qoff);
    {
        u64 sums = 0, sqs = 0;
#pragma unroll 1
        for (int ep = 0; ep < 32; ep++) {
            float q0 = dot64p(wS + (2 * ep)     * 32, x2);
            float q1 = dot64p(wS + (2 * ep + 1) * 32, x2);
            u64 cv = fmul2(pack2(q0, q1), myb[ep]);
            myb[ep] = cv;
            sums = fadd2(sums, cv);
            sqs  = ffma2(cv, cv, sqs);
        }
        float sum = hsum2(sums);
        float sq  = hsum2(sqs);
        float mu  = sum * (1.0f / 64.0f);
        float var = sq * (1.0f / 64.0f) - mu * mu;
        float rs  = rsqrtf(var + EPSf);
        u64 rsp = pack2(rs, rs);
        u64 cp  = pack2(-mu * rs, -mu * rs);
        const u64* l1w = pS + 64;
        const u64* l1b = pS + 96;
#pragma unroll
        for (int ep = 0; ep < 32; ep++) {
            u64 t = ffma2(myb[ep], rsp, cp);
            x2[ep] = ffma2(t, l1w[ep], l1b[ep]);
        }
    }

    __syncthreads();
    stageW(wS, W1, D2m * Dm, tid);
    __syncthreads();

    // ================= Phase B: h1 = ln1cv @ W1^T, LN2 =================
    {
        u64 sums = 0, sqs = 0;
#pragma unroll 1
        for (int ep = 0; ep < 64; ep += 2) {
            u64 h0 = pack2(dot64p(wS + (2 * ep)     * 32, x2),
                           dot64p(wS + (2 * ep + 1) * 32, x2));
            u64 h1 = pack2(dot64p(wS + (2 * ep + 2) * 32, x2),
                           dot64p(wS + (2 * ep + 3) * 32, x2));
            ulonglong2 st; st.x = h0; st.y = h1;
            *(ulonglong2*)(myb + ep) = st;
            sums = fadd2(sums, fadd2(h0, h1));
            sqs  = ffma2(h0, h0, sqs);
            sqs  = ffma2(h1, h1, sqs);
        }
        float sum = hsum2(sums);
        float sq  = hsum2(sqs);
        float mu  = sum * (1.0f / 128.0f);
        float var = sq * (1.0f / 128.0f) - mu * mu;
        float rs  = rsqrtf(var + EPSf);
        u64 rsp = pack2(rs, rs);
        u64 cp  = pack2(-mu * rs, -mu * rs);
        const u64* l2w = pS + 128;
        const u64* l2b = pS + 192;
#pragma unroll 1
        for (int ep = 0; ep < 64; ep += 2) {
            ulonglong2 t = *(ulonglong2*)(myb + ep);
            t.x = ffma2(ffma2(t.x, rsp, cp), l2w[ep],     l2b[ep]);
            t.y = ffma2(ffma2(t.y, rsp, cp), l2w[ep + 1], l2b[ep + 1]);
            *(ulonglong2*)(myb + ep) = t;
        }
    }

    __syncthreads();
    stageW(wS, W2, Dm * D2m, tid);
    __syncthreads();

    // ================= Phase C: out = ln2h1 @ W2^T + b2 =================
    {
#pragma unroll 1
        for (int d = 0; d < Dm; d += 4) {
            const ulonglong2* w0 = (const ulonglong2*)(wS + (d + 0) * 64);
            const ulonglong2* w1 = (const ulonglong2*)(wS + (d + 1) * 64);
            const ulonglong2* w2 = (const ulonglong2*)(wS + (d + 2) * 64);
            const ulonglong2* w3 = (const ulonglong2*)(wS + (d + 3) * 64);
            u64 a0[4] = {0, 0, 0, 0};
            u64 a1[4] = {0, 0, 0, 0};
#pragma unroll
            for (int j = 0; j < 32; j++) {
                ulonglong2 hp = *(const ulonglong2*)(myb + 2 * j);
                ulonglong2 p0 = w0[j];
                a0[0] = ffma2(p0.x, hp.x, a0[0]); a1[0] = ffma2(p0.y, hp.y, a1[0]);
                ulonglong2 p1 = w1[j];
                a0[1] = ffma2(p1.x, hp.x, a0[1]); a1[1] = ffma2(p1.y, hp.y, a1[1]);
                ulonglong2 p2 = w2[j];
                a0[2] = ffma2(p2.x, hp.x, a0[2]); a1[2] = ffma2(p2.y, hp.y, a1[2]);
                ulonglong2 p3 = w3[j];
                a0[3] = ffma2(p3.x, hp.x, a0[3]); a1[3] = ffma2(p3.y, hp.y, a1[3]);
            }
            float4 o;
            o.x = hsum2(fadd2(a0[0], a1[0])) + pSf[512 + d + 0];
            o.y = hsum2(fadd2(a0[1], a1[1])) + pSf[512 + d + 1];
            o.z = hsum2(fadd2(a0[2], a1[2])) + pSf[512 + d + 2];
            o.w = hsum2(fadd2(a0[3], a1[3])) + pSf[512 + d + 3];
            *(float4*)(OUT + qoff + d) = o;
        }
    }
}

extern "C" void kernel_launch(void* const* d_in, const int* in_sizes, int n_in,
                              void* d_out, int out_size) {
    const float* Qin  = (const float*)d_in[0];
    const float* Kin  = (const float*)d_in[1];
    const float* Vin  = (const float*)d_in[2];
    const float* MEM  = (const float*)d_in[3];
    const float* Wq   = (const float*)d_in[4];
    const float* Wk   = (const float*)d_in[5];
    const float* Wv   = (const float*)d_in[6];
    const float* FG   = (const float*)d_in[7];
    const float* LN1W = (const float*)d_in[8];
    const float* LN1B = (const float*)d_in[9];
    const float* W1   = (const float*)d_in[10];
    const float* LN2W = (const float*)d_in[11];
    const float* LN2B = (const float*)d_in[12];
    const float* W2   = (const float*)d_in[13];
    const float* B2   = (const float*)d_in[14];

    float* OUT = (float*)d_out;                         // [B,S,HID]
    float* CM  = OUT + (size_t)B_ * S_ * H_ * Dm;       // [B,H,S,D]

    // dynamic smem: 4096 (weights) + 320 (params) + TPB*BUFSTRIDE (scratch) u64
    const int smem_bytes = (4096 + 320 + TPB * BUFSTRIDE) * 8;
    cudaFuncSetAttribute(mhba_fused_kernel,
                         cudaFuncAttributeMaxDynamicSharedMemorySize, smem_bytes);

    mhba_fused_kernel<<<NROWS / TPB, TPB, smem_bytes>>>(
        Qin, Kin, Vin, MEM, Wq, Wk, Wv, FG,
        LN1W, LN1B, W1, LN2W, LN2B, W2, B2, OUT, CM);
}

// round 4
// speedup vs baseline: 6.0861x; 3.3590x over previous
#include <cuda_runtime.h>
#include <cstdint>

#define B_    8
#define S_    4096
#define H_    16
#define NTILES 4096      // (B*H*S)/128
#define TPB   256        // 8 warps, each warp owns 16 rows of the 128-row tile
#define NWARP 8
#define GRID  148
#define EPSf  1e-5f

typedef uint32_t u32;
typedef uint64_t u64;

// ---------------- SMEM layout (bytes) ----------------
// B-fragments, pre-split bf16 hi/lo, per-lane order: [m][reg0/1][lane] as u64 {hi_pair | lo_pair<<32}
#define OFF_WK   0            // 32 mma positions  * 2 regs * 32 lanes * 8B = 16384
#define OFF_WV   16384
#define OFF_WQ   32768
#define OFF_W1   49152        // 64 positions = 32768
#define OFF_W2   81920        // 64 positions = 32768
#define OFF_PRM  114688       // fg[64], l1w[64], l1b[64], b2[64], l2w[128], l2b[128] floats
#define SMEM_TOTAL (114688 + 512 * 4)

// split (e,o) fp32 pair into bf16x2 hi (lo half = e) and bf16x2 residual lo
__device__ __forceinline__ void split2(float e, float o, u32 &hi, u32 &lo) {
    u32 h; asm("cvt.rn.bf16x2.f32 %0, %1, %2;" : "=r"(h) : "f"(o), "f"(e));
    float he = __uint_as_float(h << 16);
    float ho = __uint_as_float(h & 0xffff0000u);
    float re = e - he, ro = o - ho;
    asm("cvt.rn.bf16x2.f32 %0, %1, %2;" : "=r"(lo) : "f"(ro), "f"(re));
    hi = h;
}

__device__ __forceinline__ void mma16816(float &c0, float &c1, float &c2, float &c3,
                                         u32 a0, u32 a1, u32 a2, u32 a3, u32 b0, u32 b1) {
    asm volatile("mma.sync.aligned.m16n8k16.row.col.f32.bf16.bf16.f32 "
                 "{%0,%1,%2,%3}, {%4,%5,%6,%7}, {%8,%9}, {%0,%1,%2,%3};"
                 : "+f"(c0), "+f"(c1), "+f"(c2), "+f"(c3)
                 : "r"(a0), "r"(a1), "r"(a2), "r"(a3), "r"(b0), "r"(b1));
}

// GEMM: c[NT][4] (fp32, caller-inited), A frags ah/al[KT*4], B frags in smem.
template<int NT, int KT>
__device__ __forceinline__ void do_gemm(float (*c)[4], const u32 *ah, const u32 *al,
                                        const u64 *Bsm, int lane) {
#pragma unroll
    for (int kt = 0; kt < KT; kt++) {
#pragma unroll
        for (int nt = 0; nt < NT; nt++) {
            const int m = nt * KT + kt;
            u64 p0 = Bsm[(2 * m) * 32 + lane];
            u64 p1 = Bsm[(2 * m + 1) * 32 + lane];
            u32 b0h = (u32)p0, b0l = (u32)(p0 >> 32);
            u32 b1h = (u32)p1, b1l = (u32)(p1 >> 32);
            mma16816(c[nt][0], c[nt][1], c[nt][2], c[nt][3],
                     ah[4*kt], ah[4*kt+1], ah[4*kt+2], ah[4*kt+3], b0h, b1h);
            mma16816(c[nt][0], c[nt][1], c[nt][2], c[nt][3],
                     ah[4*kt], ah[4*kt+1], ah[4*kt+2], ah[4*kt+3], b0l, b1l);
            mma16816(c[nt][0], c[nt][1], c[nt][2], c[nt][3],
                     al[4*kt], al[4*kt+1], al[4*kt+2], al[4*kt+3], b0h, b1h);
        }
    }
}

// Stage weight matrix W [N][K] row-major fp32 -> per-lane B fragments (split) in smem.
__device__ __forceinline__ void stageB(u64 *dst, const float * __restrict__ W,
                                       int NT, int KT, int K, int wid, int lane) {
    const int g = lane >> 2, t = lane & 3;
#pragma unroll 1
    for (int m = wid; m < NT * KT; m += NWARP) {
        int nt = m / KT, kt = m - nt * KT;
        const float *row = W + (nt * 8 + g) * K + kt * 16 + 2 * t;
        u32 h0, l0, h1, l1;
        split2(row[0], row[1], h0, l0);
        split2(row[8], row[9], h1, l1);
        dst[(2 * m) * 32 + lane]     = (u64)h0 | ((u64)l0 << 32);
        dst[(2 * m + 1) * 32 + lane] = (u64)h1 | ((u64)l1 << 32);
    }
}

// Load one kt-step of A (16 fp32 across rows g,g+8) from two gmem row pointers, split.
__device__ __forceinline__ void loadA_kt(const float * __restrict__ r0,
                                         const float * __restrict__ r1,
                                         int t, u32 *ah, u32 *al) {
    float2 e0 = *(const float2 *)(r0 + 2 * t);
    float2 e1 = *(const float2 *)(r1 + 2 * t);
    float2 e2 = *(const float2 *)(r0 + 2 * t + 8);
    float2 e3 = *(const float2 *)(r1 + 2 * t + 8);
    split2(e0.x, e0.y, ah[0], al[0]);
    split2(e1.x, e1.y, ah[1], al[1]);
    split2(e2.x, e2.y, ah[2], al[2]);
    split2(e3.x, e3.y, ah[3], al[3]);
}

__device__ __forceinline__ float qreduce(float v) {
    v += __shfl_xor_sync(0xffffffffu, v, 1);
    v += __shfl_xor_sync(0xffffffffu, v, 2);
    return v;
}

__device__ __forceinline__ int qoff_of(int row) {
    int s = row & (S_ - 1);
    int h = (row >> 12) & (H_ - 1);
    int b = row >> 16;
    return (((b << 12) | s) << 10) + (h << 6);
}

extern __shared__ char smem[];

__global__ void __launch_bounds__(TPB, 1) mhba_hmma_kernel(
    const float* __restrict__ Qin, const float* __restrict__ Kin,
    const float* __restrict__ Vin, const float* __restrict__ MEM,
    const float* __restrict__ Wq,  const float* __restrict__ Wk,
    const float* __restrict__ Wv,  const float* __restrict__ FG,
    const float* __restrict__ LN1W, const float* __restrict__ LN1B,
    const float* __restrict__ W1,
    const float* __restrict__ LN2W, const float* __restrict__ LN2B,
    const float* __restrict__ W2,  const float* __restrict__ B2,
    float* __restrict__ OUT, float* __restrict__ CM)
{
    const int tid  = threadIdx.x;
    const int wid  = tid >> 5;
    const int lane = tid & 31;
    const int g = lane >> 2, t = lane & 3;

    float *pf = (float *)(smem + OFF_PRM);
    if (tid < 64) {
        pf[tid]       = FG[tid];
        pf[64 + tid]  = LN1W[tid];
        pf[128 + tid] = LN1B[tid];
        pf[192 + tid] = B2[tid];
    }
    if (tid < 128) {
        pf[256 + tid] = LN2W[tid];
        pf[384 + tid] = LN2B[tid];
    }
    stageB((u64 *)(smem + OFF_WK), Wk, 8,  4, 64,  wid, lane);
    stageB((u64 *)(smem + OFF_WV), Wv, 8,  4, 64,  wid, lane);
    stageB((u64 *)(smem + OFF_WQ), Wq, 8,  4, 64,  wid, lane);
    stageB((u64 *)(smem + OFF_W1), W1, 16, 4, 64,  wid, lane);
    stageB((u64 *)(smem + OFF_W2), W2, 8,  8, 128, wid, lane);
    __syncthreads();

    const u64 *BWk = (const u64 *)(smem + OFF_WK);
    const u64 *BWv = (const u64 *)(smem + OFF_WV);
    const u64 *BWq = (const u64 *)(smem + OFF_WQ);
    const u64 *BW1 = (const u64 *)(smem + OFF_W1);
    const u64 *BW2 = (const u64 *)(smem + OFF_W2);

#pragma unroll 1
    for (int tile = blockIdx.x; tile < NTILES; tile += gridDim.x) {
        const int rbase = tile * 128 + wid * 16;
        const int row0 = rbase + g;
        const int row1 = row0 + 8;
        const int q0 = qoff_of(row0), q1 = qoff_of(row1);
        const int m0 = row0 << 6,     m1 = row1 << 6;

        u32 ah[16], al[16];

        // ---------- GEMM1: kp = Xk @ Wk^T ----------
#pragma unroll
        for (int kt = 0; kt < 4; kt++)
            loadA_kt(Kin + q0 + kt * 16, Kin + q1 + kt * 16, t, ah + 4 * kt, al + 4 * kt);
        float ckp[8][4];
#pragma unroll
        for (int i = 0; i < 8; i++) { ckp[i][0]=0.f; ckp[i][1]=0.f; ckp[i][2]=0.f; ckp[i][3]=0.f; }
        do_gemm<8, 4>(ckp, ah, al, BWk, lane);

        // ---------- GEMM2: vp = Xv @ Wv^T ----------
#pragma unroll
        for (int kt = 0; kt < 4; kt++)
            loadA_kt(Vin + q0 + kt * 16, Vin + q1 + kt * 16, t, ah + 4 * kt, al + 4 * kt);
        float cvp[8][4];
#pragma unroll
        for (int i = 0; i < 8; i++) { cvp[i][0]=0.f; cvp[i][1]=0.f; cvp[i][2]=0.f; cvp[i][3]=0.f; }
        do_gemm<8, 4>(cvp, ah, al, BWv, lane);

        // ---------- gate -> cur_mem (store), keep cm in cvp ----------
#pragma unroll
        for (int nt = 0; nt < 8; nt++) {
            const int colb = nt * 8 + 2 * t;
            float2 fg = *(const float2 *)(pf + colb);
            float2 mA = *(const float2 *)(MEM + m0 + colb);
            float2 mB = *(const float2 *)(MEM + m1 + colb);
            float fmx, cell;
            fmx  = fg.x * mA.x; cell = fmaf(ckp[nt][0], cvp[nt][0], fmx);
            float c0 = fmaf(1.f - fg.x, cell, fmx);
            fmx  = fg.y * mA.y; cell = fmaf(ckp[nt][1], cvp[nt][1], fmx);
            float c1 = fmaf(1.f - fg.y, cell, fmx);
            fmx  = fg.x * mB.x; cell = fmaf(ckp[nt][2], cvp[nt][2], fmx);
            float c2 = fmaf(1.f - fg.x, cell, fmx);
            fmx  = fg.y * mB.y; cell = fmaf(ckp[nt][3], cvp[nt][3], fmx);
            float c3 = fmaf(1.f - fg.y, cell, fmx);
            *(float2 *)(CM + m0 + colb) = make_float2(c0, c1);
            *(float2 *)(CM + m1 + colb) = make_float2(c2, c3);
            cvp[nt][0] = c0; cvp[nt][1] = c1; cvp[nt][2] = c2; cvp[nt][3] = c3;
        }

        // ---------- GEMM3: qp = Xq @ Wq^T ----------
#pragma unroll
        for (int kt = 0; kt < 4; kt++)
            loadA_kt(Qin + q0 + kt * 16, Qin + q1 + kt * 16, t, ah + 4 * kt, al + 4 * kt);
#pragma unroll
        for (int i = 0; i < 8; i++) { ckp[i][0]=0.f; ckp[i][1]=0.f; ckp[i][2]=0.f; ckp[i][3]=0.f; }
        do_gemm<8, 4>(ckp, ah, al, BWq, lane);

        // ---------- cv = qp * cm ; LN1 ----------
#pragma unroll
        for (int nt = 0; nt < 8; nt++) {
            cvp[nt][0] *= ckp[nt][0]; cvp[nt][1] *= ckp[nt][1];
            cvp[nt][2] *= ckp[nt][2]; cvp[nt][3] *= ckp[nt][3];
        }
        {
            float s0 = 0.f, sq0 = 0.f, s1 = 0.f, sq1 = 0.f;
#pragma unroll
            for (int nt = 0; nt < 8; nt++) {
                s0 += cvp[nt][0] + cvp[nt][1];
                sq0 = fmaf(cvp[nt][0], cvp[nt][0], fmaf(cvp[nt][1], cvp[nt][1], sq0));
                s1 += cvp[nt][2] + cvp[nt][3];
                sq1 = fmaf(cvp[nt][2], cvp[nt][2], fmaf(cvp[nt][3], cvp[nt][3], sq1));
            }
            s0 = qreduce(s0); sq0 = qreduce(sq0);
            s1 = qreduce(s1); sq1 = qreduce(sq1);
            float mu0 = s0 * (1.f / 64.f);
            float rs0 = rsqrtf(sq0 * (1.f / 64.f) - mu0 * mu0 + EPSf);
            float mu1 = s1 * (1.f / 64.f);
            float rs1 = rsqrtf(sq1 * (1.f / 64.f) - mu1 * mu1 + EPSf);
#pragma unroll
            for (int nt = 0; nt < 8; nt++) {
                const int colb = nt * 8 + 2 * t;
                float2 w = *(const float2 *)(pf + 64 + colb);
                float2 bb = *(const float2 *)(pf + 128 + colb);
                cvp[nt][0] = fmaf((cvp[nt][0] - mu0) * rs0, w.x, bb.x);
                cvp[nt][1] = fmaf((cvp[nt][1] - mu0) * rs0, w.y, bb.y);
                cvp[nt][2] = fmaf((cvp[nt][2] - mu1) * rs1, w.x, bb.x);
                cvp[nt][3] = fmaf((cvp[nt][3] - mu1) * rs1, w.y, bb.y);
            }
        }
        // convert ln1(cv) -> A frags (K=64)
#pragma unroll
        for (int kt = 0; kt < 4; kt++) {
            split2(cvp[2*kt][0],   cvp[2*kt][1],   ah[4*kt+0], al[4*kt+0]);
            split2(cvp[2*kt][2],   cvp[2*kt][3],   ah[4*kt+1], al[4*kt+1]);
            split2(cvp[2*kt+1][0], cvp[2*kt+1][1], ah[4*kt+2], al[4*kt+2]);
            split2(cvp[2*kt+1][2], cvp[2*kt+1][3], ah[4*kt+3], al[4*kt+3]);
        }

        // ---------- GEMM4: h1 = ln1cv @ W1^T  (N=128) ----------
        float h1[16][4];
#pragma unroll
        for (int i = 0; i < 16; i++) { h1[i][0]=0.f; h1[i][1]=0.f; h1[i][2]=0.f; h1[i][3]=0.f; }
        do_gemm<16, 4>(h1, ah, al, BW1, lane);

        // ---------- LN2 ----------
        {
            float s0 = 0.f, sq0 = 0.f, s1 = 0.f, sq1 = 0.f;
#pragma unroll
            for (int nt = 0; nt < 16; nt++) {
                s0 += h1[nt][0] + h1[nt][1];
                sq0 = fmaf(h1[nt][0], h1[nt][0], fmaf(h1[nt][1], h1[nt][1], sq0));
                s1 += h1[nt][2] + h1[nt][3];
                sq1 = fmaf(h1[nt][2], h1[nt][2], fmaf(h1[nt][3], h1[nt][3], sq1));
            }
            s0 = qreduce(s0); sq0 = qreduce(sq0);
            s1 = qreduce(s1); sq1 = qreduce(sq1);
            float mu0 = s0 * (1.f / 128.f);
            float rs0 = rsqrtf(sq0 * (1.f / 128.f) - mu0 * mu0 + EPSf);
            float mu1 = s1 * (1.f / 128.f);
            float rs1 = rsqrtf(sq1 * (1.f / 128.f) - mu1 * mu1 + EPSf);
#pragma unroll
            for (int nt = 0; nt < 16; nt++) {
                const int colb = nt * 8 + 2 * t;
                float2 w = *(const float2 *)(pf + 256 + colb);
                float2 bb = *(const float2 *)(pf + 384 + colb);
                h1[nt][0] = fmaf((h1[nt][0] - mu0) * rs0, w.x, bb.x);
                h1[nt][1] = fmaf((h1[nt][1] - mu0) * rs0, w.y, bb.y);
                h1[nt][2] = fmaf((h1[nt][2] - mu1) * rs1, w.x, bb.x);
                h1[nt][3] = fmaf((h1[nt][3] - mu1) * rs1, w.y, bb.y);
            }
        }
        // convert ln2(h1) -> A frags (K=128)
        u32 ah2[32], al2[32];
#pragma unroll
        for (int kt = 0; kt < 8; kt++) {
            split2(h1[2*kt][0],   h1[2*kt][1],   ah2[4*kt+0], al2[4*kt+0]);
            split2(h1[2*kt][2],   h1[2*kt][3],   ah2[4*kt+1], al2[4*kt+1]);
            split2(h1[2*kt+1][0], h1[2*kt+1][1], ah2[4*kt+2], al2[4*kt+2]);
            split2(h1[2*kt+1][2], h1[2*kt+1][3], ah2[4*kt+3], al2[4*kt+3]);
        }

        // ---------- GEMM5: out = ln2h1 @ W2^T + b2 ----------
        float co[8][4];
#pragma unroll
        for (int i = 0; i < 8; i++) { co[i][0]=0.f; co[i][1]=0.f; co[i][2]=0.f; co[i][3]=0.f; }
        do_gemm<8, 8>(co, ah2, al2, BW2, lane);

#pragma unroll
        for (int nt = 0; nt < 8; nt++) {
            const int colb = nt * 8 + 2 * t;
            float2 b2v = *(const float2 *)(pf + 192 + colb);
            *(float2 *)(OUT + q0 + colb) = make_float2(co[nt][0] + b2v.x, co[nt][1] + b2v.y);
            *(float2 *)(OUT + q1 + colb) = make_float2(co[nt][2] + b2v.x, co[nt][3] + b2v.y);
        }
    }
}

extern "C" void kernel_launch(void* const* d_in, const int* in_sizes, int n_in,
                              void* d_out, int out_size) {
    const float* Qin  = (const float*)d_in[0];
    const float* Kin  = (const float*)d_in[1];
    const float* Vin  = (const float*)d_in[2];
    const float* MEM  = (const float*)d_in[3];
    const float* Wq   = (const float*)d_in[4];
    const float* Wk   = (const float*)d_in[5];
    const float* Wv   = (const float*)d_in[6];
    const float* FG   = (const float*)d_in[7];
    const float* LN1W = (const float*)d_in[8];
    const float* LN1B = (const float*)d_in[9];
    const float* W1   = (const float*)d_in[10];
    const float* LN2W = (const float*)d_in[11];
    const float* LN2B = (const float*)d_in[12];
    const float* W2   = (const float*)d_in[13];
    const float* B2   = (const float*)d_in[14];

    float* OUT = (float*)d_out;                       // [B,S,HID]
    float* CM  = OUT + (size_t)B_ * S_ * H_ * 64;     // [B,H,S,D]

    static int attr_set = 0;
    if (!attr_set) {
        cudaFuncSetAttribute(mhba_hmma_kernel,
                             cudaFuncAttributeMaxDynamicSharedMemorySize, SMEM_TOTAL);
        attr_set = 1;
    }

    mhba_hmma_kernel<<<GRID, TPB, SMEM_TOTAL>>>(
        Qin, Kin, Vin, MEM, Wq, Wk, Wv, FG,
        LN1W, LN1B, W1, LN2W, LN2B, W2, B2, OUT, CM);
}

// round 5
// speedup vs baseline: 7.8357x; 1.2875x over previous
#include <cuda_runtime.h>
#include <cstdint>

#define B_    8
#define S_    4096
#define H_    16
#define NTILES 2048      // (B*H*S)/256
#define TPB   512        // 16 warps, each warp owns 16 rows of the 256-row tile
#define NWARP 16
#define GRID  148
#define EPSf  1e-5f

typedef uint32_t u32;
typedef uint64_t u64;

// ---------------- SMEM layout (bytes) ----------------
// B-fragments per mma position, per lane: uint4 {b0h, b1h, b0l, b1l}
// position m -> dst[m*32 + lane] (16B per lane per position)
#define OFF_WK   0            // 32 positions * 32 lanes * 16B = 16384
#define OFF_WV   16384
#define OFF_WQ   32768
#define OFF_W1   49152        // 64 positions = 32768
#define OFF_W2   81920        // 64 positions = 32768
#define OFF_PRM  114688       // fg[64], l1w[64], l1b[64], b2[64], l2w[128], l2b[128] floats
#define SMEM_TOTAL (114688 + 512 * 4)

// split (e,o) fp32 pair into bf16x2 hi (lo half = e) and bf16x2 residual lo
__device__ __forceinline__ void split2(float e, float o, u32 &hi, u32 &lo) {
    u32 h; asm("cvt.rn.bf16x2.f32 %0, %1, %2;" : "=r"(h) : "f"(o), "f"(e));
    float he = __uint_as_float(h << 16);
    float ho = __uint_as_float(h & 0xffff0000u);
    float re = e - he, ro = o - ho;
    asm("cvt.rn.bf16x2.f32 %0, %1, %2;" : "=r"(lo) : "f"(ro), "f"(re));
    hi = h;
}

__device__ __forceinline__ void mma16816(float &c0, float &c1, float &c2, float &c3,
                                         u32 a0, u32 a1, u32 a2, u32 a3, u32 b0, u32 b1) {
    asm volatile("mma.sync.aligned.m16n8k16.row.col.f32.bf16.bf16.f32 "
                 "{%0,%1,%2,%3}, {%4,%5,%6,%7}, {%8,%9}, {%0,%1,%2,%3};"
                 : "+f"(c0), "+f"(c1), "+f"(c2), "+f"(c3)
                 : "r"(a0), "r"(a1), "r"(a2), "r"(a3), "r"(b0), "r"(b1));
}

// GEMM: c[NT][4] (fp32, caller-inited), A frags ah/al[KT*4], B frags in smem (uint4/lane).
template<int NT, int KT>
__device__ __forceinline__ void do_gemm(float (*c)[4], const u32 *ah, const u32 *al,
                                        const uint4 *Bsm, int lane) {
#pragma unroll
    for (int kt = 0; kt < KT; kt++) {
#pragma unroll
        for (int nt = 0; nt < NT; nt++) {
            const int m = nt * KT + kt;
            uint4 p = Bsm[m * 32 + lane];   // {b0h, b1h, b0l, b1l}
            mma16816(c[nt][0], c[nt][1], c[nt][2], c[nt][3],
                     ah[4*kt], ah[4*kt+1], ah[4*kt+2], ah[4*kt+3], p.x, p.y);
            mma16816(c[nt][0], c[nt][1], c[nt][2], c[nt][3],
                     ah[4*kt], ah[4*kt+1], ah[4*kt+2], ah[4*kt+3], p.z, p.w);
            mma16816(c[nt][0], c[nt][1], c[nt][2], c[nt][3],
                     al[4*kt], al[4*kt+1], al[4*kt+2], al[4*kt+3], p.x, p.y);
        }
    }
}

// Stage weight matrix W [N][K] row-major fp32 -> per-lane B fragments (split) in smem.
__device__ __forceinline__ void stageB(uint4 *dst, const float * __restrict__ W,
                                       int NT, int KT, int K, int wid, int lane) {
    const int g = lane >> 2, t = lane & 3;
#pragma unroll 1
    for (int m = wid; m < NT * KT; m += NWARP) {
        int nt = m / KT, kt = m - nt * KT;
        const float *row = W + (nt * 8 + g) * K + kt * 16 + 2 * t;
        u32 h0, l0, h1, l1;
        split2(row[0], row[1], h0, l0);
        split2(row[8], row[9], h1, l1);
        uint4 v = { h0, h1, l0, l1 };
        dst[m * 32 + lane] = v;
    }
}

// Load one kt-step of A (16 fp32 across rows g,g+8) from two gmem row pointers, split.
__device__ __forceinline__ void loadA_kt(const float * __restrict__ r0,
                                         const float * __restrict__ r1,
                                         int t, u32 *ah, u32 *al) {
    float2 e0 = *(const float2 *)(r0 + 2 * t);
    float2 e1 = *(const float2 *)(r1 + 2 * t);
    float2 e2 = *(const float2 *)(r0 + 2 * t + 8);
    float2 e3 = *(const float2 *)(r1 + 2 * t + 8);
    split2(e0.x, e0.y, ah[0], al[0]);
    split2(e1.x, e1.y, ah[1], al[1]);
    split2(e2.x, e2.y, ah[2], al[2]);
    split2(e3.x, e3.y, ah[3], al[3]);
}

__device__ __forceinline__ float qreduce(float v) {
    v += __shfl_xor_sync(0xffffffffu, v, 1);
    v += __shfl_xor_sync(0xffffffffu, v, 2);
    return v;
}

__device__ __forceinline__ int qoff_of(int row) {
    int s = row & (S_ - 1);
    int h = (row >> 12) & (H_ - 1);
    int b = row >> 16;
    return (((b << 12) | s) << 10) + (h << 6);
}

extern __shared__ char smem[];

__global__ void __launch_bounds__(TPB, 1) mhba_hmma_kernel(
    const float* __restrict__ Qin, const float* __restrict__ Kin,
    const float* __restrict__ Vin, const float* __restrict__ MEM,
    const float* __restrict__ Wq,  const float* __restrict__ Wk,
    const float* __restrict__ Wv,  const float* __restrict__ FG,
    const float* __restrict__ LN1W, const float* __restrict__ LN1B,
    const float* __restrict__ W1,
    const float* __restrict__ LN2W, const float* __restrict__ LN2B,
    const float* __restrict__ W2,  const float* __restrict__ B2,
    float* __restrict__ OUT, float* __restrict__ CM)
{
    const int tid  = threadIdx.x;
    const int wid  = tid >> 5;
    const int lane = tid & 31;
    const int g = lane >> 2, t = lane & 3;

    float *pf = (float *)(smem + OFF_PRM);
    if (tid < 64) {
        pf[tid]       = FG[tid];
        pf[64 + tid]  = LN1W[tid];
        pf[128 + tid] = LN1B[tid];
        pf[192 + tid] = B2[tid];
    }
    if (tid < 128) {
        pf[256 + tid] = LN2W[tid];
        pf[384 + tid] = LN2B[tid];
    }
    stageB((uint4 *)(smem + OFF_WK), Wk, 8,  4, 64,  wid, lane);
    stageB((uint4 *)(smem + OFF_WV), Wv, 8,  4, 64,  wid, lane);
    stageB((uint4 *)(smem + OFF_WQ), Wq, 8,  4, 64,  wid, lane);
    stageB((uint4 *)(smem + OFF_W1), W1, 16, 4, 64,  wid, lane);
    stageB((uint4 *)(smem + OFF_W2), W2, 8,  8, 128, wid, lane);
    __syncthreads();

    const uint4 *BWk = (const uint4 *)(smem + OFF_WK);
    const uint4 *BWv = (const uint4 *)(smem + OFF_WV);
    const uint4 *BWq = (const uint4 *)(smem + OFF_WQ);
    const uint4 *BW1 = (const uint4 *)(smem + OFF_W1);
    const uint4 *BW2 = (const uint4 *)(smem + OFF_W2);

#pragma unroll 1
    for (int tile = blockIdx.x; tile < NTILES; tile += gridDim.x) {
        const int rbase = tile * 256 + wid * 16;
        const int row0 = rbase + g;
        const int row1 = row0 + 8;
        const int q0 = qoff_of(row0), q1 = qoff_of(row1);
        const int m0 = row0 << 6,     m1 = row1 << 6;

        u32 ah[16], al[16];

        // ---------- GEMM1: kp = Xk @ Wk^T ----------
#pragma unroll
        for (int kt = 0; kt < 4; kt++)
            loadA_kt(Kin + q0 + kt * 16, Kin + q1 + kt * 16, t, ah + 4 * kt, al + 4 * kt);
        float ckp[8][4];
#pragma unroll
        for (int i = 0; i < 8; i++) { ckp[i][0]=0.f; ckp[i][1]=0.f; ckp[i][2]=0.f; ckp[i][3]=0.f; }
        do_gemm<8, 4>(ckp, ah, al, BWk, lane);

        // ---------- GEMM2: vp = Xv @ Wv^T ----------
#pragma unroll
        for (int kt = 0; kt < 4; kt++)
            loadA_kt(Vin + q0 + kt * 16, Vin + q1 + kt * 16, t, ah + 4 * kt, al + 4 * kt);
        float cvp[8][4];
#pragma unroll
        for (int i = 0; i < 8; i++) { cvp[i][0]=0.f; cvp[i][1]=0.f; cvp[i][2]=0.f; cvp[i][3]=0.f; }
        do_gemm<8, 4>(cvp, ah, al, BWv, lane);

        // ---------- gate -> cur_mem (store), keep cm in cvp ----------
#pragma unroll
        for (int nt = 0; nt < 8; nt++) {
            const int colb = nt * 8 + 2 * t;
            float2 fg = *(const float2 *)(pf + colb);
            float2 mA = *(const float2 *)(MEM + m0 + colb);
            float2 mB = *(const float2 *)(MEM + m1 + colb);
            float fmx, cell;
            fmx  = fg.x * mA.x; cell = fmaf(ckp[nt][0], cvp[nt][0], fmx);
            float c0 = fmaf(1.f - fg.x, cell, fmx);
            fmx  = fg.y * mA.y; cell = fmaf(ckp[nt][1], cvp[nt][1], fmx);
            float c1 = fmaf(1.f - fg.y, cell, fmx);
            fmx  = fg.x * mB.x; cell = fmaf(ckp[nt][2], cvp[nt][2], fmx);
            float c2 = fmaf(1.f - fg.x, cell, fmx);
            fmx  = fg.y * mB.y; cell = fmaf(ckp[nt][3], cvp[nt][3], fmx);
            float c3 = fmaf(1.f - fg.y, cell, fmx);
            *(float2 *)(CM + m0 + colb) = make_float2(c0, c1);
            *(float2 *)(CM + m1 + colb) = make_float2(c2, c3);
            cvp[nt][0] = c0; cvp[nt][1] = c1; cvp[nt][2] = c2; cvp[nt][3] = c3;
        }

        // ---------- GEMM3: qp = Xq @ Wq^T ----------
#pragma unroll
        for (int kt = 0; kt < 4; kt++)
            loadA_kt(Qin + q0 + kt * 16, Qin + q1 + kt * 16, t, ah + 4 * kt, al + 4 * kt);
#pragma unroll
        for (int i = 0; i < 8; i++) { ckp[i][0]=0.f; ckp[i][1]=0.f; ckp[i][2]=0.f; ckp[i][3]=0.f; }
        do_gemm<8, 4>(ckp, ah, al, BWq, lane);

        // ---------- cv = qp * cm ; LN1 ----------
#pragma unroll
        for (int nt = 0; nt < 8; nt++) {
            cvp[nt][0] *= ckp[nt][0]; cvp[nt][1] *= ckp[nt][1];
            cvp[nt][2] *= ckp[nt][2]; cvp[nt][3] *= ckp[nt][3];
        }
        {
            float s0 = 0.f, sq0 = 0.f, s1 = 0.f, sq1 = 0.f;
#pragma unroll
            for (int nt = 0; nt < 8; nt++) {
                s0 += cvp[nt][0] + cvp[nt][1];
                sq0 = fmaf(cvp[nt][0], cvp[nt][0], fmaf(cvp[nt][1], cvp[nt][1], sq0));
                s1 += cvp[nt][2] + cvp[nt][3];
                sq1 = fmaf(cvp[nt][2], cvp[nt][2], fmaf(cvp[nt][3], cvp[nt][3], sq1));
            }
            s0 = qreduce(s0); sq0 = qreduce(sq0);
            s1 = qreduce(s1); sq1 = qreduce(sq1);
            float mu0 = s0 * (1.f / 64.f);
            float rs0 = rsqrtf(sq0 * (1.f / 64.f) - mu0 * mu0 + EPSf);
            float mu1 = s1 * (1.f / 64.f);
            float rs1 = rsqrtf(sq1 * (1.f / 64.f) - mu1 * mu1 + EPSf);
#pragma unroll
            for (int nt = 0; nt < 8; nt++) {
                const int colb = nt * 8 + 2 * t;
                float2 w = *(const float2 *)(pf + 64 + colb);
                float2 bb = *(const float2 *)(pf + 128 + colb);
                cvp[nt][0] = fmaf((cvp[nt][0] - mu0) * rs0, w.x, bb.x);
                cvp[nt][1] = fmaf((cvp[nt][1] - mu0) * rs0, w.y, bb.y);
                cvp[nt][2] = fmaf((cvp[nt][2] - mu1) * rs1, w.x, bb.x);
                cvp[nt][3] = fmaf((cvp[nt][3] - mu1) * rs1, w.y, bb.y);
            }
        }
        // convert ln1(cv) -> A frags (K=64)
#pragma unroll
        for (int kt = 0; kt < 4; kt++) {
            split2(cvp[2*kt][0],   cvp[2*kt][1],   ah[4*kt+0], al[4*kt+0]);
            split2(cvp[2*kt][2],   cvp[2*kt][3],   ah[4*kt+1], al[4*kt+1]);
            split2(cvp[2*kt+1][0], cvp[2*kt+1][1], ah[4*kt+2], al[4*kt+2]);
            split2(cvp[2*kt+1][2], cvp[2*kt+1][3], ah[4*kt+3], al[4*kt+3]);
        }

        // ---------- GEMM4: h1 = ln1cv @ W1^T  (N=128) ----------
        float h1[16][4];
#pragma unroll
        for (int i = 0; i < 16; i++) { h1[i][0]=0.f; h1[i][1]=0.f; h1[i][2]=0.f; h1[i][3]=0.f; }
        do_gemm<16, 4>(h1, ah, al, BW1, lane);

        // ---------- LN2 ----------
        {
            float s0 = 0.f, sq0 = 0.f, s1 = 0.f, sq1 = 0.f;
#pragma unroll
            for (int nt = 0; nt < 16; nt++) {
                s0 += h1[nt][0] + h1[nt][1];
                sq0 = fmaf(h1[nt][0], h1[nt][0], fmaf(h1[nt][1], h1[nt][1], sq0));
                s1 += h1[nt][2] + h1[nt][3];
                sq1 = fmaf(h1[nt][2], h1[nt][2], fmaf(h1[nt][3], h1[nt][3], sq1));
            }
            s0 = qreduce(s0); sq0 = qreduce(sq0);
            s1 = qreduce(s1); sq1 = qreduce(sq1);
            float mu0 = s0 * (1.f / 128.f);
            float rs0 = rsqrtf(sq0 * (1.f / 128.f) - mu0 * mu0 + EPSf);
            float mu1 = s1 * (1.f / 128.f);
            float rs1 = rsqrtf(sq1 * (1.f / 128.f) - mu1 * mu1 + EPSf);
#pragma unroll
            for (int nt = 0; nt < 16; nt++) {
                const int colb = nt * 8 + 2 * t;
                float2 w = *(const float2 *)(pf + 256 + colb);
                float2 bb = *(const float2 *)(pf + 384 + colb);
                h1[nt][0] = fmaf((h1[nt][0] - mu0) * rs0, w.x, bb.x);
                h1[nt][1] = fmaf((h1[nt][1] - mu0) * rs0, w.y, bb.y);
                h1[nt][2] = fmaf((h1[nt][2] - mu1) * rs1, w.x, bb.x);
                h1[nt][3] = fmaf((h1[nt][3] - mu1) * rs1, w.y, bb.y);
            }
        }
        // convert ln2(h1) -> A frags (K=128); h1 registers die as frags are produced
        u32 ah2[32], al2[32];
#pragma unroll
        for (int kt = 0; kt < 8; kt++) {
            split2(h1[2*kt][0],   h1[2*kt][1],   ah2[4*kt+0], al2[4*kt+0]);
            split2(h1[2*kt][2],   h1[2*kt][3],   ah2[4*kt+1], al2[4*kt+1]);
            split2(h1[2*kt+1][0], h1[2*kt+1][1], ah2[4*kt+2], al2[4*kt+2]);
            split2(h1[2*kt+1][2], h1[2*kt+1][3], ah2[4*kt+3], al2[4*kt+3]);
        }

        // ---------- GEMM5: out = ln2h1 @ W2^T + b2 ----------
        float co[8][4];
#pragma unroll
        for (int i = 0; i < 8; i++) { co[i][0]=0.f; co[i][1]=0.f; co[i][2]=0.f; co[i][3]=0.f; }
        do_gemm<8, 8>(co, ah2, al2, BW2, lane);

#pragma unroll
        for (int nt = 0; nt < 8; nt++) {
            const int colb = nt * 8 + 2 * t;
            float2 b2v = *(const float2 *)(pf + 192 + colb);
            *(float2 *)(OUT + q0 + colb) = make_float2(co[nt][0] + b2v.x, co[nt][1] + b2v.y);
            *(float2 *)(OUT + q1 + colb) = make_float2(co[nt][2] + b2v.x, co[nt][3] + b2v.y);
        }
    }
}

extern "C" void kernel_launch(void* const* d_in, const int* in_sizes, int n_in,
                              void* d_out, int out_size) {
    const float* Qin  = (const float*)d_in[0];
    const float* Kin  = (const float*)d_in[1];
    const float* Vin  = (const float*)d_in[2];
    const float* MEM  = (const float*)d_in[3];
    const float* Wq   = (const float*)d_in[4];
    const float* Wk   = (const float*)d_in[5];
    const float* Wv   = (const float*)d_in[6];
    const float* FG   = (const float*)d_in[7];
    const float* LN1W = (const float*)d_in[8];
    const float* LN1B = (const float*)d_in[9];
    const float* W1   = (const float*)d_in[10];
    const float* LN2W = (const float*)d_in[11];
    const float* LN2B = (const float*)d_in[12];
    const float* W2   = (const float*)d_in[13];
    const float* B2   = (const float*)d_in[14];

    float* OUT = (float*)d_out;                       // [B,S,HID]
    float* CM  = OUT + (size_t)B_ * S_ * H_ * 64;     // [B,H,S,D]

    static int attr_set = 0;
    if (!attr_set) {
        cudaFuncSetAttribute(mhba_hmma_kernel,
                             cudaFuncAttributeMaxDynamicSharedMemorySize, SMEM_TOTAL);
        attr_set = 1;
    }

    mhba_hmma_kernel<<<GRID, TPB, SMEM_TOTAL>>>(
        Qin, Kin, Vin, MEM, Wq, Wk, Wv, FG,
        LN1W, LN1B, W1, LN2W, LN2B, W2, B2, OUT, CM);
}